// round 9
// baseline (speedup 1.0000x reference)
#include <cuda_runtime.h>
#include <math.h>

// RoPE: out[..., 2i]   = cos(a)*x[...,2i] - sin(a)*x[...,2i+1]
//       out[..., 2i+1] = sin(a)*x[...,2i] + cos(a)*x[...,2i+1]
// a = pos * 10000^(-i/32),  D_K=64, pos in [0, 4096)
//
// 1 MiB cos/sin table (4096 pos x 32 freqs, float2), rebuilt each call.
// Table build: fp32 Cody-Waite mod-2pi reduction (exact for k<=652) + MUFU
// __sinf/__cosf on the reduced arg -> ~3e-7 abs error, ~4us instead of ~16us
// of accurate-sincosf slow path.
// Main kernel: block-tiled, 4 interleaved float4s per thread, streaming hints.

#define HALF 32            // D_K / 2
#define MAX_POS 4096

__device__ float2 g_rope_table[MAX_POS * HALF];   // cos in .x, sin in .y, [pos][freq]
__device__ int    g_pos_is_i64;                   // 1 if positions are 8-byte ints

__global__ void setup_kernel(const int* __restrict__ posw) {
    int idx = blockIdx.x * blockDim.x + threadIdx.x;

    // thread 0: dtype detection. int64 values < 2^32 -> every odd word is 0.
    // int32 sorted-random in [0,4096): 32 consecutive zero odd-words ~impossible.
    if (idx == 0) {
        int i64 = 1;
        #pragma unroll
        for (int k = 0; k < 32; k++)
            if (posw[2 * k + 1] != 0) { i64 = 0; break; }
        g_pos_is_i64 = i64;
    }

    if (idx >= MAX_POS * HALF) return;
    int p = idx >> 5;       // position
    int i = idx & 31;       // frequency index
    // inv_freq rounded to fp32 (matches reference's fp32 theta**(-2i/64))
    float inv_freq = (float)exp(-((double)i / 32.0) * log(10000.0));
    float x = (float)p * inv_freq;                  // fl(p*f), same as reference

    // Cody-Waite reduction mod 2*pi: x in [0, 4096] -> k <= 652 (10 bits).
    // C0 = 6.28125 has 8 mantissa bits -> k*C0 exact; x - k*C0 exact (cancellation).
    // Residual error ~ k * ulp(C1) ~ 8e-8 rad.
    const float INV_2PI = 0.15915494309189535f;
    const float C0 = 6.28125f;
    const float C1 = 1.9353071795864769e-3f;        // 2*pi - 6.28125
    float k = rintf(x * INV_2PI);
    float r = fmaf(-k, C0, x);
    r = fmaf(-k, C1, r);                            // r in [-pi, pi]

    // MUFU sin/cos on reduced arg: abs err ~2^-21 on [-pi, pi]
    float s = __sinf(r);
    float c = __cosf(r);
    g_rope_table[idx] = make_float2(c, s);
}

__global__ void __launch_bounds__(256) rope_kernel(
    const float4* __restrict__ x,
    const int*    __restrict__ posw,   // raw 32-bit view of positions buffer
    float4*       __restrict__ out,
    int n4)
{
    const int TILE = 1024;             // 4 chunks x 256 threads
    int base = blockIdx.x * TILE + threadIdx.x;
    int i64 = g_pos_is_i64;

    int   idxv[4];
    int   pv[4];
    float4 xv[4];
    float4 tv[4];
    bool  ok[4];

    // front-batch: indices + pos loads + x loads (independent LDGs)
    #pragma unroll
    for (int u = 0; u < 4; u++) {
        int idx = base + u * 256;
        idxv[u] = idx;
        ok[u] = (idx < n4);
        int row = idx >> 4;
        int p = ok[u] ? (i64 ? __ldg(&posw[2 * row]) : __ldg(&posw[row])) : 0;
        pv[u] = min(max(p, 0), MAX_POS - 1);        // defensive clamp: no OOB ever
        if (ok[u]) xv[u] = __ldcs(&x[idx]);
    }

    // table loads (dependent on pos, batched together)
    #pragma unroll
    for (int u = 0; u < 4; u++) {
        int j = idxv[u] & 15;
        const float4* tp = reinterpret_cast<const float4*>(
            &g_rope_table[pv[u] * HALF + 2 * j]);
        tv[u] = __ldg(tp);                          // (cos0, sin0, cos1, sin1)
    }

    // rotate + streaming store
    #pragma unroll
    for (int u = 0; u < 4; u++) {
        if (!ok[u]) continue;
        float4 t = tv[u], xa = xv[u], o;
        o.x = fmaf(t.x, xa.x, -t.y * xa.y);         // cos*x1 - sin*x2
        o.y = fmaf(t.y, xa.x,  t.x * xa.y);         // sin*x1 + cos*x2
        o.z = fmaf(t.z, xa.z, -t.w * xa.w);
        o.w = fmaf(t.w, xa.z,  t.z * xa.w);
        __stcs(&out[idxv[u]], o);
    }
}

extern "C" void kernel_launch(void* const* d_in, const int* in_sizes, int n_in,
                              void* d_out, int out_size) {
    const float4* x    = (const float4*)d_in[0];
    const int*    posw = (const int*)d_in[1];    // raw word view; dtype detected on device
    float4*       out  = (float4*)d_out;

    int n  = in_sizes[0];          // 8*16*4096*64 = 33,554,432
    int n4 = n >> 2;               // float4 count = 8,388,608

    setup_kernel<<<(MAX_POS * HALF + 511) / 512, 512>>>(posw);

    int blocks = (n4 + 1023) / 1024;              // 8192
    rope_kernel<<<blocks, 256>>>(x, posw, out, n4);
}